// round 11
// baseline (speedup 1.0000x reference)
#include <cuda_runtime.h>
#include <math.h>
#include <cstdint>

#define HH 1024
#define WW 1024
#define CC 128
#define NW 16                 // warps per block = columns per block (incl. 2 halo)
#define TPB (NW * 32)
#define COUT (NW - 2)         // 14 output columns per block
#define ROWG 128              // rows per block
#define BATCH 32              // rows per deferred dot-reduce burst
#define DPPAD 36              // dp row stride (16B aligned for LDS.128)

#define VS_FLOATS (2 * 2 * NW * CC)        // 8192
#define DP_FLOATS (NW * BATCH * DPPAD)     // 18432
#define DSO_FLOATS (NW * 33)               // 528
#define SMEM_FLOATS (VS_FLOATS + DP_FLOATS + DSO_FLOATS)

// ---- packed f32x2 primitives (sm_103a; PTX-only) ----
__device__ __forceinline__ uint64_t f2mul(uint64_t a, uint64_t b) {
    uint64_t r; asm("mul.rn.f32x2 %0,%1,%2;" : "=l"(r) : "l"(a), "l"(b)); return r;
}
__device__ __forceinline__ uint64_t f2add(uint64_t a, uint64_t b) {
    uint64_t r; asm("add.rn.f32x2 %0,%1,%2;" : "=l"(r) : "l"(a), "l"(b)); return r;
}
__device__ __forceinline__ uint64_t f2fma(uint64_t a, uint64_t b, uint64_t c) {
    uint64_t r; asm("fma.rn.f32x2 %0,%1,%2,%3;" : "=l"(r) : "l"(a), "l"(b), "l"(c)); return r;
}
__device__ __forceinline__ uint64_t pack2(float x, float y) {
    uint64_t r; asm("mov.b64 %0,{%1,%2};" : "=l"(r) : "f"(x), "f"(y)); return r;
}
__device__ __forceinline__ float hsum2(uint64_t v) {
    float x, y; asm("mov.b64 {%0,%1},%2;" : "=f"(x), "=f"(y) : "l"(v)); return x + y;
}
__device__ __forceinline__ float dot4p(ulonglong2 v) {
    return hsum2(f2fma(v.y, v.y, f2mul(v.x, v.x)));
}

// reduce TWO independent values across the warp in one shared butterfly (6 SHFL)
__device__ __forceinline__ float2 redux2(float a, float b, int lane) {
    const unsigned full = 0xffffffffu;
    float z = (lane < 16) ? a : b;
    float w = (lane < 16) ? b : a;
    w = __shfl_xor_sync(full, w, 16);
    z += w;
    #pragma unroll
    for (int o = 8; o > 0; o >>= 1)
        z += __shfl_xor_sync(full, z, o);
    float t = __shfl_xor_sync(full, z, 16);
    float sa = (lane < 16) ? z : t;
    float sb = (lane < 16) ? t : z;
    return make_float2(sa, sb);
}

template<bool SAFE>
__device__ __forceinline__ void run_body(
    const float* __restrict__ in, float* __restrict__ out,
    float* vsb, float* dp, float* dso)
{
    const int lane = threadIdx.x & 31;
    const int wid  = threadIdx.x >> 5;
    const int col  = blockIdx.x * COUT + wid - 1;     // wid 0 / NW-1 = halo
    const bool colok = SAFE ? ((unsigned)col < (unsigned)WW) : true;
    const bool inner = (wid >= 1) && (wid <= COUT);
    const int r0 = blockIdx.y * ROWG;

    float* dprow = dp + wid * (BATCH * DPPAD);

    const float* gcol = in + (size_t)col * CC + lane * 4;
    const size_t rowstep = (size_t)WW * CC;
    auto ld = [&](int h) -> ulonglong2 {
        if constexpr (SAFE) {
            ulonglong2 v; v.x = 0ull; v.y = 0ull;
            if (colok && (unsigned)h < (unsigned)HH)
                v = *reinterpret_cast<const ulonglong2*>(gcol + (size_t)h * rowstep);
            return v;
        } else {
            return *reinterpret_cast<const ulonglong2*>(gcol + (size_t)h * rowstep);
        }
    };
    auto scalev = [&](ulonglong2 v, float inv) -> ulonglong2 {
        const uint64_t ip = pack2(inv, inv);
        ulonglong2 r; r.x = f2mul(v.x, ip); r.y = f2mul(v.y, ip); return r;
    };

    // ---- preamble: normalize rows r0-1, r0 (paired reduce); 4 rows staged ----
    ulonglong2 xnA, xnB;
    {
        ulonglong2 ra = ld(r0 - 1), rb = ld(r0);
        float2 ss = redux2(dot4p(ra), dot4p(rb), lane);
        xnA = scalev(ra, (ss.x >= 1e-16f) ? rsqrtf(ss.x) : 1e8f);
        xnB = scalev(rb, (ss.y >= 1e-16f) ? rsqrtf(ss.y) : 1e8f);
    }
    ulonglong2 stg[2][2];
    stg[0][0] = ld(r0 + 1);  stg[0][1] = ld(r0 + 2);
    stg[1][0] = ld(r0 + 3);  stg[1][1] = ld(r0 + 4);

    #pragma unroll 2
    for (int k = 0; k < ROWG / 2; k++) {
        const int i = 2 * k;
        const int h = r0 + i;
        const int p = k & 1;

        // normalize rows h+1, h+2 with ONE paired butterfly
        ulonglong2 s0 = stg[p][0], s1 = stg[p][1];
        float2 ss = redux2(dot4p(s0), dot4p(s1), lane);
        const ulonglong2 xnC = scalev(s0, (ss.x >= 1e-16f) ? rsqrtf(ss.x) : 1e8f);
        const ulonglong2 xnD = scalev(s1, (ss.y >= 1e-16f) ? rsqrtf(ss.y) : 1e8f);
        stg[p][0] = ld(h + 5);                 // refill, 4 rows ahead
        stg[p][1] = ld(h + 6);

        ulonglong2 v0, v1;                     // vertical 3-sums (packed)
        v0.x = f2add(f2add(xnA.x, xnB.x), xnC.x);
        v0.y = f2add(f2add(xnA.y, xnB.y), xnC.y);
        v1.x = f2add(f2add(xnB.x, xnC.x), xnD.x);
        v1.y = f2add(f2add(xnB.y, xnC.y), xnD.y);

        float* base0 = vsb + ((p * 2 + 0) * NW + wid) * CC + lane * 4;
        float* base1 = base0 + NW * CC;
        *reinterpret_cast<ulonglong2*>(base0) = v0;
        *reinterpret_cast<ulonglong2*>(base1) = v1;
        __syncthreads();                       // one barrier per 2 rows

        // cooperative, coalesced store of the PREVIOUS 32-row batch
        if ((i & 31) == 0 && i > 0) {
            const int t = threadIdx.x;
            if (t < BATCH * COUT) {
                const int row = t / COUT;
                const int c   = t - row * COUT;
                const int oc  = blockIdx.x * COUT + c;
                if (!SAFE || oc < WW)
                    out[(size_t)(h - 32 + row) * WW + oc] = dso[(c + 1) * 33 + row];
            }
        }

        if (inner) {                           // warp-uniform
            const ulonglong2 l0 = *reinterpret_cast<const ulonglong2*>(base0 - CC);
            const ulonglong2 q0 = *reinterpret_cast<const ulonglong2*>(base0 + CC);
            const ulonglong2 l1 = *reinterpret_cast<const ulonglong2*>(base1 - CC);
            const ulonglong2 q1 = *reinterpret_cast<const ulonglong2*>(base1 + CC);

            uint64_t t0 = f2mul(xnB.x, f2add(f2add(l0.x, v0.x), q0.x));
            t0 = f2fma(xnB.y, f2add(f2add(l0.y, v0.y), q0.y), t0);
            uint64_t t1 = f2mul(xnC.x, f2add(f2add(l1.x, v1.x), q1.x));
            t1 = f2fma(xnC.y, f2add(f2add(l1.y, v1.y), q1.y), t1);

            dprow[(i & 31) * DPPAD + lane]       = hsum2(t0);   // defer lane-reduce
            dprow[((i + 1) & 31) * DPPAD + lane] = hsum2(t1);

            if ((i & 31) == 30) {              // batch of 32 rows complete
                __syncwarp();
                // packed-pair transpose-sum: lane sums its row of 32 partials
                uint64_t a = 0ull, b = 0ull;   // bit pattern of (+0.f,+0.f)
                const float* rowp = dprow + lane * DPPAD;
                #pragma unroll
                for (int j = 0; j < BATCH; j += 4) {
                    const ulonglong2 u = *reinterpret_cast<const ulonglong2*>(rowp + j);
                    a = f2add(a, u.x);
                    b = f2add(b, u.y);
                }
                dso[wid * 33 + lane] = hsum2(f2add(a, b)) - 1.0f;
            }
        }
        xnA = xnC;  xnB = xnD;
    }

    // trailing batch (rows r0+96 .. r0+127)
    __syncthreads();
    const int t = threadIdx.x;
    if (t < BATCH * COUT) {
        const int row = t / COUT;
        const int c   = t - row * COUT;
        const int oc  = blockIdx.x * COUT + c;
        if (!SAFE || oc < WW)
            out[(size_t)(r0 + 96 + row) * WW + oc] = dso[(c + 1) * 33 + row];
    }
}

__global__ void __launch_bounds__(TPB, 2)
cos_sim_stream(const float* __restrict__ in, float* __restrict__ out)
{
    extern __shared__ float smem[];
    float* vsb = smem;
    float* dp  = smem + VS_FLOATS;
    float* dso = dp + DP_FLOATS;

    const bool edge = (blockIdx.x == 0) | (blockIdx.x == gridDim.x - 1) |
                      (blockIdx.y == 0) | (blockIdx.y == gridDim.y - 1);
    if (edge) run_body<true>(in, out, vsb, dp, dso);
    else      run_body<false>(in, out, vsb, dp, dso);
}

extern "C" void kernel_launch(void* const* d_in, const int* in_sizes, int n_in,
                              void* d_out, int out_size)
{
    const float* in = (const float*)d_in[0];
    float* out = (float*)d_out;

    const size_t smem_bytes = SMEM_FLOATS * sizeof(float);   // ~108.6 KB
    cudaFuncSetAttribute(cos_sim_stream,
                         cudaFuncAttributeMaxDynamicSharedMemorySize,
                         (int)smem_bytes);

    dim3 grid((WW + COUT - 1) / COUT, HH / ROWG);   // 74 x 8
    cos_sim_stream<<<grid, TPB, smem_bytes>>>(in, out);
}

// round 12
// speedup vs baseline: 1.0116x; 1.0116x over previous
#include <cuda_runtime.h>
#include <math.h>
#include <cstdint>

#define HH 1024
#define WW 1024
#define CC 128
#define NW 8                  // warps per block = columns per block (incl. 2 halo)
#define TPB (NW * 32)
#define COUT (NW - 2)         // 6 output columns per block
#define ROWG 128              // rows per block
#define BATCH 32              // rows per deferred dot-reduce burst

#define VS_FLOATS (2 * 2 * NW * CC)        // 4096  (parity, rowpair, warp, ch)
#define DP_FLOATS (NW * BATCH * 33)        // 8448  (warp, rowslot, lane+pad)
#define SMEM_FLOATS (VS_FLOATS + DP_FLOATS)

// ---- packed f32x2 primitives (sm_103a; PTX-only, ptxas won't auto-fuse) ----
__device__ __forceinline__ uint64_t f2mul(uint64_t a, uint64_t b) {
    uint64_t r; asm("mul.rn.f32x2 %0,%1,%2;" : "=l"(r) : "l"(a), "l"(b)); return r;
}
__device__ __forceinline__ uint64_t f2add(uint64_t a, uint64_t b) {
    uint64_t r; asm("add.rn.f32x2 %0,%1,%2;" : "=l"(r) : "l"(a), "l"(b)); return r;
}
__device__ __forceinline__ uint64_t f2fma(uint64_t a, uint64_t b, uint64_t c) {
    uint64_t r; asm("fma.rn.f32x2 %0,%1,%2,%3;" : "=l"(r) : "l"(a), "l"(b), "l"(c)); return r;
}
__device__ __forceinline__ uint64_t pack2(float x, float y) {
    uint64_t r; asm("mov.b64 %0,{%1,%2};" : "=l"(r) : "f"(x), "f"(y)); return r;
}
__device__ __forceinline__ float hsum2(uint64_t v) {
    float x, y; asm("mov.b64 {%0,%1},%2;" : "=f"(x), "=f"(y) : "l"(v)); return x + y;
}
__device__ __forceinline__ float dot4p(ulonglong2 v) {
    return hsum2(f2fma(v.y, v.y, f2mul(v.x, v.x)));
}

// reduce TWO independent values across the warp in one shared butterfly (6 SHFL)
__device__ __forceinline__ float2 redux2(float a, float b, int lane) {
    const unsigned full = 0xffffffffu;
    float z = (lane < 16) ? a : b;
    float w = (lane < 16) ? b : a;
    w = __shfl_xor_sync(full, w, 16);
    z += w;
    #pragma unroll
    for (int o = 8; o > 0; o >>= 1)
        z += __shfl_xor_sync(full, z, o);
    float t = __shfl_xor_sync(full, z, 16);
    float sa = (lane < 16) ? z : t;
    float sb = (lane < 16) ? t : z;
    return make_float2(sa, sb);
}

__global__ void __launch_bounds__(TPB, 4)
cos_sim_stream(const float* __restrict__ in, float* __restrict__ out)
{
    extern __shared__ float smem[];
    float* vsb = smem;                 // vertical-sum exchange ring
    float* dp  = smem + VS_FLOATS;     // per-warp deferred dot partials

    const int lane = threadIdx.x & 31;
    const int wid  = threadIdx.x >> 5;
    const int col  = blockIdx.x * COUT + wid - 1;     // wid 0 / NW-1 = halo
    const bool colok = ((unsigned)col < (unsigned)WW);
    const bool inner = (wid >= 1) && (wid <= COUT);
    const bool outok = colok && inner;
    const int r0 = blockIdx.y * ROWG;

    float* dprow = dp + wid * (BATCH * 33);

    const float* gcol = in + (size_t)col * CC + lane * 4;
    const size_t rowstep = (size_t)WW * CC;
    auto ld = [&](int h) -> ulonglong2 {
        ulonglong2 v; v.x = 0ull; v.y = 0ull;
        if (colok && (unsigned)h < (unsigned)HH)
            v = *reinterpret_cast<const ulonglong2*>(gcol + (size_t)h * rowstep);
        return v;
    };
    auto scalev = [&](ulonglong2 v, float inv) -> ulonglong2 {
        const uint64_t ip = pack2(inv, inv);
        ulonglong2 r; r.x = f2mul(v.x, ip); r.y = f2mul(v.y, ip); return r;
    };

    // ---- preamble: normalize rows r0-1, r0 (paired reduce); 4 rows staged ----
    ulonglong2 xnA, xnB;
    {
        ulonglong2 ra = ld(r0 - 1), rb = ld(r0);
        float2 ss = redux2(dot4p(ra), dot4p(rb), lane);
        xnA = scalev(ra, (ss.x >= 1e-16f) ? rsqrtf(ss.x) : 1e8f);
        xnB = scalev(rb, (ss.y >= 1e-16f) ? rsqrtf(ss.y) : 1e8f);
    }
    ulonglong2 stg[2][2];
    stg[0][0] = ld(r0 + 1);  stg[0][1] = ld(r0 + 2);
    stg[1][0] = ld(r0 + 3);  stg[1][1] = ld(r0 + 4);

    #pragma unroll 2
    for (int k = 0; k < ROWG / 2; k++) {
        const int i = 2 * k;
        const int h = r0 + i;
        const int p = k & 1;

        // normalize rows h+1, h+2 with ONE paired butterfly
        ulonglong2 s0 = stg[p][0], s1 = stg[p][1];
        float2 ss = redux2(dot4p(s0), dot4p(s1), lane);
        const ulonglong2 xnC = scalev(s0, (ss.x >= 1e-16f) ? rsqrtf(ss.x) : 1e8f);
        const ulonglong2 xnD = scalev(s1, (ss.y >= 1e-16f) ? rsqrtf(ss.y) : 1e8f);
        stg[p][0] = ld(h + 5);                 // refill, 4 rows ahead
        stg[p][1] = ld(h + 6);

        ulonglong2 v0, v1;                     // vertical 3-sums (packed)
        v0.x = f2add(f2add(xnA.x, xnB.x), xnC.x);
        v0.y = f2add(f2add(xnA.y, xnB.y), xnC.y);
        v1.x = f2add(f2add(xnB.x, xnC.x), xnD.x);
        v1.y = f2add(f2add(xnB.y, xnC.y), xnD.y);

        float* base0 = vsb + ((p * 2 + 0) * NW + wid) * CC + lane * 4;
        float* base1 = base0 + NW * CC;
        *reinterpret_cast<ulonglong2*>(base0) = v0;
        *reinterpret_cast<ulonglong2*>(base1) = v1;
        __syncthreads();                       // one 8-warp barrier per 2 rows

        if (inner) {                           // warp-uniform
            const ulonglong2 l0 = *reinterpret_cast<const ulonglong2*>(base0 - CC);
            const ulonglong2 q0 = *reinterpret_cast<const ulonglong2*>(base0 + CC);
            const ulonglong2 l1 = *reinterpret_cast<const ulonglong2*>(base1 - CC);
            const ulonglong2 q1 = *reinterpret_cast<const ulonglong2*>(base1 + CC);

            uint64_t t0 = f2mul(xnB.x, f2add(f2add(l0.x, v0.x), q0.x));
            t0 = f2fma(xnB.y, f2add(f2add(l0.y, v0.y), q0.y), t0);
            uint64_t t1 = f2mul(xnC.x, f2add(f2add(l1.x, v1.x), q1.x));
            t1 = f2fma(xnC.y, f2add(f2add(l1.y, v1.y), q1.y), t1);

            dprow[(i & 31) * 33 + lane]       = hsum2(t0);   // defer lane-reduce
            dprow[((i + 1) & 31) * 33 + lane] = hsum2(t1);

            if ((i & 31) == 30) {              // batch of 32 rows complete
                __syncwarp();
                if (outok) {
                    float s = 0.f;
                    #pragma unroll
                    for (int j = 0; j < 32; j++) s += dprow[lane * 33 + j];
                    out[(size_t)(h - 30 + lane) * WW + col] = s - 1.0f;
                }
                __syncwarp();
            }
        }
        xnA = xnC;  xnB = xnD;
    }
}

extern "C" void kernel_launch(void* const* d_in, const int* in_sizes, int n_in,
                              void* d_out, int out_size)
{
    const float* in = (const float*)d_in[0];
    float* out = (float*)d_out;

    const size_t smem_bytes = SMEM_FLOATS * sizeof(float);   // ~50.2 KB
    cudaFuncSetAttribute(cos_sim_stream,
                         cudaFuncAttributeMaxDynamicSharedMemorySize,
                         (int)smem_bytes);

    dim3 grid((WW + COUT - 1) / COUT, HH / ROWG);   // 171 x 8
    cos_sim_stream<<<grid, TPB, smem_bytes>>>(in, out);
}